// round 7
// baseline (speedup 1.0000x reference)
#include <cuda_runtime.h>
#include <float.h>

// ChamferDist (adv->ori): loss = mean_b( w_b * mean_k( min_j ||adv[bk]-ori[bj]||^2 ) )
//
// min_j dist = a2_k + min_j (b2_j - 2 a_k.b_j).
// R7: R6 inner math (2 LDS.128 + 12 FFMA2 + 8 FMNMX per ori-pair, 4 adv
// pts/thread) with two fixes driven by R6 ncu:
//   1) __launch_bounds__(256,4) -> <=64 regs -> occ 4 -> all 512 CTAs
//      resident in ONE wave (no 68-CTA tail wave).
//   2) Hot path specialized to a compile-time 128-trip pair loop (K%JS==0
//      case), unroll 8 -> removes dynamic-bound loop overhead.
// Combine unchanged: scratch[point][16] -> group last-CTA -> final scalar.
// Single launch, deterministic, graph-replay safe.

#define CD_THREADS 256
#define CD_PTS     4
#define CD_JS      16
#define CD_KCHUNK  1024          // CD_THREADS * CD_PTS
#define CD_JCHUNK  256
#define CD_PAIRS   128           // CD_JCHUNK / 2
#define CD_MAX_SCRATCH (1 << 21) // floats (8 MB)
#define CD_MAX_GROUPS  1024

__device__ float        g_cd_scratch[CD_MAX_SCRATCH];
__device__ float        g_cd_group[CD_MAX_GROUPS];
__device__ unsigned int g_cd_tile_count[CD_MAX_GROUPS];
__device__ unsigned int g_cd_final_count;

__device__ __forceinline__ unsigned long long pack_dup(float v) {
    unsigned long long r;
    asm("mov.b64 %0, {%1, %1};" : "=l"(r) : "f"(v));
    return r;
}
__device__ __forceinline__ unsigned long long fma2(unsigned long long a,
                                                   unsigned long long b,
                                                   unsigned long long c) {
    unsigned long long d;
    asm("fma.rn.f32x2 %0, %1, %2, %3;" : "=l"(d) : "l"(a), "l"(b), "l"(c));
    return d;
}

__global__ __launch_bounds__(CD_THREADS, 4)
void chamfer_main_kernel(const float* __restrict__ adv,
                         const float* __restrict__ ori,
                         const float* __restrict__ w,
                         float* __restrict__ out,
                         int B, int K, int ktiles, float scale) {
    __shared__ float4 sXY[CD_PAIRS];
    __shared__ float4 sZW[CD_PAIRS];
    __shared__ float  red[CD_THREADS / 32];
    __shared__ bool   sFlag;

    const int tid = threadIdx.x;
    const int kt  = blockIdx.x % ktiles;
    const int rem = blockIdx.x / ktiles;
    const int js  = rem % CD_JS;
    const int b   = rem / CD_JS;
    const int ngroups = B * ktiles;
    const int gid = b * ktiles + kt;

    // ---- Fill smem with this CTA's ori j-chunk (pair layout) ----
    const int j0g = js * CD_JCHUNK;
    int cl = K - j0g;
    if (cl > CD_JCHUNK) cl = CD_JCHUNK;
    if (cl < 0) cl = 0;
    const int pairsPad = (cl + 1) >> 1;

    const float* __restrict__ orib = ori + (size_t)b * K * 3;
    if (tid < pairsPad) {
        const int p  = tid;
        const int j0 = 2 * p;
        const int j1 = (2 * p + 1 < cl) ? (2 * p + 1) : (cl - 1);
        const float x0 = orib[(j0g + j0) * 3 + 0];
        const float y0 = orib[(j0g + j0) * 3 + 1];
        const float z0 = orib[(j0g + j0) * 3 + 2];
        const float x1 = orib[(j0g + j1) * 3 + 0];
        const float y1 = orib[(j0g + j1) * 3 + 1];
        const float z1 = orib[(j0g + j1) * 3 + 2];
        sXY[p] = make_float4(-2.0f * x0, -2.0f * x1, -2.0f * y0, -2.0f * y1);
        sZW[p] = make_float4(-2.0f * z0, -2.0f * z1,
                             x0 * x0 + y0 * y0 + z0 * z0,
                             x1 * x1 + y1 * y1 + z1 * z1);
    }
    __syncthreads();

    // ---- 4 adv points per thread ----
    float a2[CD_PTS];
    unsigned long long axx[CD_PTS], ayy[CD_PTS], azz[CD_PTS];
#pragma unroll
    for (int u = 0; u < CD_PTS; ++u) {
        const int k = kt * CD_KCHUNK + tid + u * CD_THREADS;
        float x = 0.f, y = 0.f, z = 0.f;
        if (k < K) {
            const float* __restrict__ a = adv + ((size_t)b * K + k) * 3;
            x = a[0]; y = a[1]; z = a[2];
        }
        a2[u]  = x * x + y * y + z * z;
        axx[u] = pack_dup(x); ayy[u] = pack_dup(y); azz[u] = pack_dup(z);
    }

    float mlo[CD_PTS], mhi[CD_PTS];
#pragma unroll
    for (int u = 0; u < CD_PTS; ++u) { mlo[u] = FLT_MAX; mhi[u] = FLT_MAX; }

    const ulonglong2* __restrict__ pXY = (const ulonglong2*)sXY;
    const ulonglong2* __restrict__ pZW = (const ulonglong2*)sZW;

    if (pairsPad == CD_PAIRS) {
        // Hot path: compile-time trip count, heavy unroll.
#pragma unroll 8
        for (int p = 0; p < CD_PAIRS; ++p) {
            const ulonglong2 A = pXY[p];   // (x0,x1) , (y0,y1)
            const ulonglong2 Z = pZW[p];   // (z0,z1) , (b2_0,b2_1)
#pragma unroll
            for (int u = 0; u < CD_PTS; ++u) {
                union { unsigned long long u64; float2 f2; } t;
                t.u64 = fma2(azz[u], Z.x, Z.y);
                t.u64 = fma2(ayy[u], A.y, t.u64);
                t.u64 = fma2(axx[u], A.x, t.u64);
                mlo[u] = fminf(mlo[u], t.f2.x);
                mhi[u] = fminf(mhi[u], t.f2.y);
            }
        }
    } else {
        for (int p = 0; p < pairsPad; ++p) {
            const ulonglong2 A = pXY[p];
            const ulonglong2 Z = pZW[p];
#pragma unroll
            for (int u = 0; u < CD_PTS; ++u) {
                union { unsigned long long u64; float2 f2; } t;
                t.u64 = fma2(azz[u], Z.x, Z.y);
                t.u64 = fma2(ayy[u], A.y, t.u64);
                t.u64 = fma2(axx[u], A.x, t.u64);
                mlo[u] = fminf(mlo[u], t.f2.x);
                mhi[u] = fminf(mhi[u], t.f2.y);
            }
        }
    }

    // ---- Write partial mins (a2 folded in) ----
#pragma unroll
    for (int u = 0; u < CD_PTS; ++u) {
        const int k = kt * CD_KCHUNK + tid + u * CD_THREADS;
        if (k < K) {
            g_cd_scratch[((size_t)b * K + k) * CD_JS + js] =
                fminf(mlo[u], mhi[u]) + a2[u];
        }
    }

    // ---- Per-(b,ktile) group combine by the group's last CTA ----
    __threadfence();
    if (tid == 0) {
        const unsigned int c = atomicAdd(&g_cd_tile_count[gid], 1u);
        sFlag = (c == (unsigned int)(CD_JS - 1));
    }
    __syncthreads();
    if (!sFlag) return;
    __threadfence();

    {
        const int kbase = kt * CD_KCHUNK;
        int npts = K - kbase;
        if (npts > CD_KCHUNK) npts = CD_KCHUNK;
        const float* __restrict__ base =
            g_cd_scratch + ((size_t)b * K + kbase) * CD_JS;
        float s = 0.0f;
        for (int i = tid; i < npts; i += CD_THREADS) {
            const float4* __restrict__ pp = (const float4*)(base + (size_t)i * CD_JS);
            float mv = FLT_MAX;
#pragma unroll
            for (int q = 0; q < CD_JS / 4; ++q) {
                const float4 v = pp[q];
                mv = fminf(mv, fminf(fminf(v.x, v.y), fminf(v.z, v.w)));
            }
            s += mv;
        }
        const int lane = tid & 31, wid = tid >> 5;
#pragma unroll
        for (int off = 16; off > 0; off >>= 1)
            s += __shfl_down_sync(0xffffffffu, s, off);
        if (lane == 0) red[wid] = s;
        __syncthreads();
        if (tid == 0) {
            float v = 0.0f;
#pragma unroll
            for (int i = 0; i < CD_THREADS / 32; ++i) v += red[i];
            g_cd_group[gid] = v * w[b];
            g_cd_tile_count[gid] = 0u;   // reset for graph replay
            __threadfence();
            const unsigned int c = atomicAdd(&g_cd_final_count, 1u);
            sFlag = (c == (unsigned int)(ngroups - 1));
        }
        __syncthreads();
        if (!sFlag) return;

        // ---- Final: sum the (<=64) group sums, fixed order ----
        if (tid == 0) {
            __threadfence();
            float v = 0.0f;
#pragma unroll 8
            for (int i = 0; i < ngroups; ++i) v += g_cd_group[i];
            out[0] = v * scale;
            g_cd_final_count = 0u;       // reset for graph replay
        }
    }
}

extern "C" void kernel_launch(void* const* d_in, const int* in_sizes, int n_in,
                              void* d_out, int out_size) {
    const float* adv = (const float*)d_in[0];   // [B, K, 3] float32
    const float* ori = (const float*)d_in[1];   // [B, K, 3] float32
    const float* w   = (const float*)d_in[2];   // [B]       float32
    float* out = (float*)d_out;                 // scalar float32

    const int B = in_sizes[2];
    const int K = in_sizes[0] / (3 * B);

    const int ktiles = (K + CD_KCHUNK - 1) / CD_KCHUNK;
    const int blocks = B * CD_JS * ktiles;      // 8*16*4 = 512 @ B=8,K=4096

    const float scale = 1.0f / ((float)B * (float)K);
    chamfer_main_kernel<<<blocks, CD_THREADS>>>(adv, ori, w, out,
                                                B, K, ktiles, scale);
}

// round 8
// speedup vs baseline: 1.1507x; 1.1507x over previous
#include <cuda_runtime.h>
#include <float.h>

// ChamferDist (adv->ori): loss = mean_b( w_b * mean_k( min_j ||adv[bk]-ori[bj]||^2 ) )
//
// min_j dist = a2_k + min_j (b2_j - 2 a_k.b_j).
// R8: R6 inner math (2 LDS.128 + 12 FFMA2 + 8 FMNMX per ori-pair, 4 adv
// pts/thread, unroll 4, natural ~80 regs) with fine-grained CTA packing:
//   128 threads/CTA, KCHUNK=512, ktiles=8, JS=16 -> grid 1024 CTAs,
//   __launch_bounds__(128,6) -> 6 CTAs/SM resident, 24 warps/SM.
//   Busiest SM carries 7/1024 of work (~ideal) vs R6's 4/512.
// Exact tiling at K=4096: every CTA runs the constant 128-pair hot loop.
// Combine: scratch[point][16] -> per-(b,ktile) group last-CTA -> final scalar.
// Single launch, deterministic, graph-replay safe.

#define CD_THREADS 128
#define CD_PTS     4
#define CD_JS      16
#define CD_KCHUNK  512           // CD_THREADS * CD_PTS
#define CD_JCHUNK  256
#define CD_PAIRS   128           // CD_JCHUNK / 2
#define CD_MAX_SCRATCH (1 << 21) // floats (8 MB)
#define CD_MAX_GROUPS  1024

__device__ float        g_cd_scratch[CD_MAX_SCRATCH];
__device__ float        g_cd_group[CD_MAX_GROUPS];
__device__ unsigned int g_cd_tile_count[CD_MAX_GROUPS];
__device__ unsigned int g_cd_final_count;

__device__ __forceinline__ unsigned long long pack_dup(float v) {
    unsigned long long r;
    asm("mov.b64 %0, {%1, %1};" : "=l"(r) : "f"(v));
    return r;
}
__device__ __forceinline__ unsigned long long fma2(unsigned long long a,
                                                   unsigned long long b,
                                                   unsigned long long c) {
    unsigned long long d;
    asm("fma.rn.f32x2 %0, %1, %2, %3;" : "=l"(d) : "l"(a), "l"(b), "l"(c));
    return d;
}

__global__ __launch_bounds__(CD_THREADS, 6)
void chamfer_main_kernel(const float* __restrict__ adv,
                         const float* __restrict__ ori,
                         const float* __restrict__ w,
                         float* __restrict__ out,
                         int B, int K, int ktiles, float scale) {
    __shared__ float4 sXY[CD_PAIRS];
    __shared__ float4 sZW[CD_PAIRS];
    __shared__ float  red[CD_THREADS / 32];
    __shared__ bool   sFlag;

    const int tid = threadIdx.x;
    const int kt  = blockIdx.x % ktiles;
    const int rem = blockIdx.x / ktiles;
    const int js  = rem % CD_JS;
    const int b   = rem / CD_JS;
    const int ngroups = B * ktiles;
    const int gid = b * ktiles + kt;

    // ---- Fill smem with this CTA's ori j-chunk (pair layout) ----
    const int j0g = js * CD_JCHUNK;
    int cl = K - j0g;
    if (cl > CD_JCHUNK) cl = CD_JCHUNK;
    if (cl < 0) cl = 0;
    const int pairsPad = (cl + 1) >> 1;

    const float* __restrict__ orib = ori + (size_t)b * K * 3;
    for (int p = tid; p < pairsPad; p += CD_THREADS) {
        const int j0 = 2 * p;
        const int j1 = (2 * p + 1 < cl) ? (2 * p + 1) : (cl - 1);
        const float x0 = orib[(j0g + j0) * 3 + 0];
        const float y0 = orib[(j0g + j0) * 3 + 1];
        const float z0 = orib[(j0g + j0) * 3 + 2];
        const float x1 = orib[(j0g + j1) * 3 + 0];
        const float y1 = orib[(j0g + j1) * 3 + 1];
        const float z1 = orib[(j0g + j1) * 3 + 2];
        sXY[p] = make_float4(-2.0f * x0, -2.0f * x1, -2.0f * y0, -2.0f * y1);
        sZW[p] = make_float4(-2.0f * z0, -2.0f * z1,
                             x0 * x0 + y0 * y0 + z0 * z0,
                             x1 * x1 + y1 * y1 + z1 * z1);
    }
    __syncthreads();

    // ---- 4 adv points per thread ----
    float a2[CD_PTS];
    unsigned long long axx[CD_PTS], ayy[CD_PTS], azz[CD_PTS];
#pragma unroll
    for (int u = 0; u < CD_PTS; ++u) {
        const int k = kt * CD_KCHUNK + tid + u * CD_THREADS;
        float x = 0.f, y = 0.f, z = 0.f;
        if (k < K) {
            const float* __restrict__ a = adv + ((size_t)b * K + k) * 3;
            x = a[0]; y = a[1]; z = a[2];
        }
        a2[u]  = x * x + y * y + z * z;
        axx[u] = pack_dup(x); ayy[u] = pack_dup(y); azz[u] = pack_dup(z);
    }

    float mlo[CD_PTS], mhi[CD_PTS];
#pragma unroll
    for (int u = 0; u < CD_PTS; ++u) { mlo[u] = FLT_MAX; mhi[u] = FLT_MAX; }

    const ulonglong2* __restrict__ pXY = (const ulonglong2*)sXY;
    const ulonglong2* __restrict__ pZW = (const ulonglong2*)sZW;

    if (pairsPad == CD_PAIRS) {
        // Hot path: compile-time trip count (K multiple of JCHUNK).
#pragma unroll 4
        for (int p = 0; p < CD_PAIRS; ++p) {
            const ulonglong2 A = pXY[p];   // (x0,x1) , (y0,y1)
            const ulonglong2 Z = pZW[p];   // (z0,z1) , (b2_0,b2_1)
#pragma unroll
            for (int u = 0; u < CD_PTS; ++u) {
                union { unsigned long long u64; float2 f2; } t;
                t.u64 = fma2(azz[u], Z.x, Z.y);
                t.u64 = fma2(ayy[u], A.y, t.u64);
                t.u64 = fma2(axx[u], A.x, t.u64);
                mlo[u] = fminf(mlo[u], t.f2.x);
                mhi[u] = fminf(mhi[u], t.f2.y);
            }
        }
    } else {
#pragma unroll 4
        for (int p = 0; p < pairsPad; ++p) {
            const ulonglong2 A = pXY[p];
            const ulonglong2 Z = pZW[p];
#pragma unroll
            for (int u = 0; u < CD_PTS; ++u) {
                union { unsigned long long u64; float2 f2; } t;
                t.u64 = fma2(azz[u], Z.x, Z.y);
                t.u64 = fma2(ayy[u], A.y, t.u64);
                t.u64 = fma2(axx[u], A.x, t.u64);
                mlo[u] = fminf(mlo[u], t.f2.x);
                mhi[u] = fminf(mhi[u], t.f2.y);
            }
        }
    }

    // ---- Write partial mins (a2 folded in) ----
#pragma unroll
    for (int u = 0; u < CD_PTS; ++u) {
        const int k = kt * CD_KCHUNK + tid + u * CD_THREADS;
        if (k < K) {
            g_cd_scratch[((size_t)b * K + k) * CD_JS + js] =
                fminf(mlo[u], mhi[u]) + a2[u];
        }
    }

    // ---- Per-(b,ktile) group combine by the group's last CTA ----
    __threadfence();
    if (tid == 0) {
        const unsigned int c = atomicAdd(&g_cd_tile_count[gid], 1u);
        sFlag = (c == (unsigned int)(CD_JS - 1));
    }
    __syncthreads();
    if (!sFlag) return;
    __threadfence();

    {
        const int kbase = kt * CD_KCHUNK;
        int npts = K - kbase;
        if (npts > CD_KCHUNK) npts = CD_KCHUNK;
        const float* __restrict__ base =
            g_cd_scratch + ((size_t)b * K + kbase) * CD_JS;
        float s = 0.0f;
        for (int i = tid; i < npts; i += CD_THREADS) {
            const float4* __restrict__ pp = (const float4*)(base + (size_t)i * CD_JS);
            float mv = FLT_MAX;
#pragma unroll
            for (int q = 0; q < CD_JS / 4; ++q) {
                const float4 v = pp[q];
                mv = fminf(mv, fminf(fminf(v.x, v.y), fminf(v.z, v.w)));
            }
            s += mv;
        }
        const int lane = tid & 31, wid = tid >> 5;
#pragma unroll
        for (int off = 16; off > 0; off >>= 1)
            s += __shfl_down_sync(0xffffffffu, s, off);
        if (lane == 0) red[wid] = s;
        __syncthreads();
        if (tid == 0) {
            float v = 0.0f;
#pragma unroll
            for (int i = 0; i < CD_THREADS / 32; ++i) v += red[i];
            g_cd_group[gid] = v * w[b];
            g_cd_tile_count[gid] = 0u;   // reset for graph replay
            __threadfence();
            const unsigned int c = atomicAdd(&g_cd_final_count, 1u);
            sFlag = (c == (unsigned int)(ngroups - 1));
        }
        __syncthreads();
        if (!sFlag) return;

        // ---- Final: sum the (<=128) group sums, fixed order ----
        if (tid == 0) {
            __threadfence();
            float v = 0.0f;
#pragma unroll 8
            for (int i = 0; i < ngroups; ++i) v += g_cd_group[i];
            out[0] = v * scale;
            g_cd_final_count = 0u;       // reset for graph replay
        }
    }
}

extern "C" void kernel_launch(void* const* d_in, const int* in_sizes, int n_in,
                              void* d_out, int out_size) {
    const float* adv = (const float*)d_in[0];   // [B, K, 3] float32
    const float* ori = (const float*)d_in[1];   // [B, K, 3] float32
    const float* w   = (const float*)d_in[2];   // [B]       float32
    float* out = (float*)d_out;                 // scalar float32

    const int B = in_sizes[2];
    const int K = in_sizes[0] / (3 * B);

    const int ktiles = (K + CD_KCHUNK - 1) / CD_KCHUNK;
    const int blocks = B * CD_JS * ktiles;      // 8*16*8 = 1024 @ B=8,K=4096

    const float scale = 1.0f / ((float)B * (float)K);
    chamfer_main_kernel<<<blocks, CD_THREADS>>>(adv, ori, w, out,
                                                B, K, ktiles, scale);
}

// round 9
// speedup vs baseline: 1.1519x; 1.0010x over previous
#include <cuda_runtime.h>
#include <float.h>

// ChamferDist (adv->ori): loss = mean_b( w_b * mean_k( min_j ||adv[bk]-ori[bj]||^2 ) )
//
// min_j dist = a2_k + min_j (b2_j - 2 a_k.b_j).
// R9 = R8 (128 thr, 4 pts/thread, JS=16, grid 1024, natural regs) plus:
//   - adv prologue vectorized: 4 CONSECUTIVE pts/thread -> 3x LDG.128
//   - unroll 8 hot loop (natural registers; R7's unroll-8 was clamp-confounded)
//   - guard-free scratch writes when K % KCHUNK == 0
//   - parallel (64-thread) final group sum instead of 1-thread serial
// Combine: scratch[point][16] -> per-(b,ktile) group last-CTA -> final scalar.
// Single launch, deterministic, graph-replay safe.

#define CD_THREADS 128
#define CD_PTS     4
#define CD_JS      16
#define CD_KCHUNK  512           // CD_THREADS * CD_PTS
#define CD_JCHUNK  256
#define CD_PAIRS   128           // CD_JCHUNK / 2
#define CD_MAX_SCRATCH (1 << 21) // floats (8 MB)
#define CD_MAX_GROUPS  1024

__device__ float        g_cd_scratch[CD_MAX_SCRATCH];
__device__ float        g_cd_group[CD_MAX_GROUPS];
__device__ unsigned int g_cd_tile_count[CD_MAX_GROUPS];
__device__ unsigned int g_cd_final_count;

__device__ __forceinline__ unsigned long long pack_dup(float v) {
    unsigned long long r;
    asm("mov.b64 %0, {%1, %1};" : "=l"(r) : "f"(v));
    return r;
}
__device__ __forceinline__ unsigned long long fma2(unsigned long long a,
                                                   unsigned long long b,
                                                   unsigned long long c) {
    unsigned long long d;
    asm("fma.rn.f32x2 %0, %1, %2, %3;" : "=l"(d) : "l"(a), "l"(b), "l"(c));
    return d;
}

__global__ __launch_bounds__(CD_THREADS)
void chamfer_main_kernel(const float* __restrict__ adv,
                         const float* __restrict__ ori,
                         const float* __restrict__ w,
                         float* __restrict__ out,
                         int B, int K, int ktiles, float scale) {
    __shared__ float4 sXY[CD_PAIRS];
    __shared__ float4 sZW[CD_PAIRS];
    __shared__ float  red[CD_THREADS / 32];
    __shared__ bool   sFlag;

    const int tid = threadIdx.x;
    const int kt  = blockIdx.x % ktiles;
    const int rem = blockIdx.x / ktiles;
    const int js  = rem % CD_JS;
    const int b   = rem / CD_JS;
    const int ngroups = B * ktiles;
    const int gid = b * ktiles + kt;

    const bool exactK = (K % CD_KCHUNK) == 0;

    // ---- Fill smem with this CTA's ori j-chunk (pair layout) ----
    const int j0g = js * CD_JCHUNK;
    int cl = K - j0g;
    if (cl > CD_JCHUNK) cl = CD_JCHUNK;
    if (cl < 0) cl = 0;
    const int pairsPad = (cl + 1) >> 1;

    const float* __restrict__ orib = ori + (size_t)b * K * 3;
    for (int p = tid; p < pairsPad; p += CD_THREADS) {
        const int j0 = 2 * p;
        const int j1 = (2 * p + 1 < cl) ? (2 * p + 1) : (cl - 1);
        const float x0 = orib[(j0g + j0) * 3 + 0];
        const float y0 = orib[(j0g + j0) * 3 + 1];
        const float z0 = orib[(j0g + j0) * 3 + 2];
        const float x1 = orib[(j0g + j1) * 3 + 0];
        const float y1 = orib[(j0g + j1) * 3 + 1];
        const float z1 = orib[(j0g + j1) * 3 + 2];
        sXY[p] = make_float4(-2.0f * x0, -2.0f * x1, -2.0f * y0, -2.0f * y1);
        sZW[p] = make_float4(-2.0f * z0, -2.0f * z1,
                             x0 * x0 + y0 * y0 + z0 * z0,
                             x1 * x1 + y1 * y1 + z1 * z1);
    }
    __syncthreads();

    // ---- 4 CONSECUTIVE adv points per thread (vector loads) ----
    const int kbase = kt * CD_KCHUNK + 4 * tid;     // first of 4 consecutive pts
    float ax[CD_PTS], ay[CD_PTS], az[CD_PTS];
    const float* __restrict__ abase = adv + ((size_t)b * K + kbase) * 3;

    if (exactK && ((((size_t)abase) & 15) == 0)) {
        const float4* __restrict__ a4 = (const float4*)abase;
        const float4 q0 = a4[0];   // x0 y0 z0 x1
        const float4 q1 = a4[1];   // y1 z1 x2 y2
        const float4 q2 = a4[2];   // z2 x3 y3 z3
        ax[0] = q0.x; ay[0] = q0.y; az[0] = q0.z;
        ax[1] = q0.w; ay[1] = q1.x; az[1] = q1.y;
        ax[2] = q1.z; ay[2] = q1.w; az[2] = q2.x;
        ax[3] = q2.y; ay[3] = q2.z; az[3] = q2.w;
    } else {
#pragma unroll
        for (int u = 0; u < CD_PTS; ++u) {
            const int k = kbase + u;
            float x = 0.f, y = 0.f, z = 0.f;
            if (k < K) {
                x = abase[3 * u + 0]; y = abase[3 * u + 1]; z = abase[3 * u + 2];
            }
            ax[u] = x; ay[u] = y; az[u] = z;
        }
    }

    float a2[CD_PTS];
    unsigned long long axx[CD_PTS], ayy[CD_PTS], azz[CD_PTS];
#pragma unroll
    for (int u = 0; u < CD_PTS; ++u) {
        a2[u]  = ax[u] * ax[u] + ay[u] * ay[u] + az[u] * az[u];
        axx[u] = pack_dup(ax[u]); ayy[u] = pack_dup(ay[u]); azz[u] = pack_dup(az[u]);
    }

    float mlo[CD_PTS], mhi[CD_PTS];
#pragma unroll
    for (int u = 0; u < CD_PTS; ++u) { mlo[u] = FLT_MAX; mhi[u] = FLT_MAX; }

    const ulonglong2* __restrict__ pXY = (const ulonglong2*)sXY;
    const ulonglong2* __restrict__ pZW = (const ulonglong2*)sZW;

    if (pairsPad == CD_PAIRS) {
        // Hot path: compile-time trip count (K multiple of JCHUNK).
#pragma unroll 8
        for (int p = 0; p < CD_PAIRS; ++p) {
            const ulonglong2 A = pXY[p];   // (x0,x1) , (y0,y1)
            const ulonglong2 Z = pZW[p];   // (z0,z1) , (b2_0,b2_1)
#pragma unroll
            for (int u = 0; u < CD_PTS; ++u) {
                union { unsigned long long u64; float2 f2; } t;
                t.u64 = fma2(azz[u], Z.x, Z.y);
                t.u64 = fma2(ayy[u], A.y, t.u64);
                t.u64 = fma2(axx[u], A.x, t.u64);
                mlo[u] = fminf(mlo[u], t.f2.x);
                mhi[u] = fminf(mhi[u], t.f2.y);
            }
        }
    } else {
#pragma unroll 4
        for (int p = 0; p < pairsPad; ++p) {
            const ulonglong2 A = pXY[p];
            const ulonglong2 Z = pZW[p];
#pragma unroll
            for (int u = 0; u < CD_PTS; ++u) {
                union { unsigned long long u64; float2 f2; } t;
                t.u64 = fma2(azz[u], Z.x, Z.y);
                t.u64 = fma2(ayy[u], A.y, t.u64);
                t.u64 = fma2(axx[u], A.x, t.u64);
                mlo[u] = fminf(mlo[u], t.f2.x);
                mhi[u] = fminf(mhi[u], t.f2.y);
            }
        }
    }

    // ---- Write partial mins (a2 folded in) ----
    if (exactK) {
#pragma unroll
        for (int u = 0; u < CD_PTS; ++u) {
            g_cd_scratch[((size_t)b * K + kbase + u) * CD_JS + js] =
                fminf(mlo[u], mhi[u]) + a2[u];
        }
    } else {
#pragma unroll
        for (int u = 0; u < CD_PTS; ++u) {
            const int k = kbase + u;
            if (k < K) {
                g_cd_scratch[((size_t)b * K + k) * CD_JS + js] =
                    fminf(mlo[u], mhi[u]) + a2[u];
            }
        }
    }

    // ---- Per-(b,ktile) group combine by the group's last CTA ----
    __threadfence();
    if (tid == 0) {
        const unsigned int c = atomicAdd(&g_cd_tile_count[gid], 1u);
        sFlag = (c == (unsigned int)(CD_JS - 1));
    }
    __syncthreads();
    if (!sFlag) return;
    __threadfence();

    {
        const int kb = kt * CD_KCHUNK;
        int npts = K - kb;
        if (npts > CD_KCHUNK) npts = CD_KCHUNK;
        const float* __restrict__ base =
            g_cd_scratch + ((size_t)b * K + kb) * CD_JS;
        float s = 0.0f;
        for (int i = tid; i < npts; i += CD_THREADS) {
            const float4* __restrict__ pp = (const float4*)(base + (size_t)i * CD_JS);
            float mv = FLT_MAX;
#pragma unroll
            for (int q = 0; q < CD_JS / 4; ++q) {
                const float4 v = pp[q];
                mv = fminf(mv, fminf(fminf(v.x, v.y), fminf(v.z, v.w)));
            }
            s += mv;
        }
        const int lane = tid & 31, wid = tid >> 5;
#pragma unroll
        for (int off = 16; off > 0; off >>= 1)
            s += __shfl_down_sync(0xffffffffu, s, off);
        if (lane == 0) red[wid] = s;
        __syncthreads();
        if (tid == 0) {
            float v = 0.0f;
#pragma unroll
            for (int i = 0; i < CD_THREADS / 32; ++i) v += red[i];
            g_cd_group[gid] = v * w[b];
            g_cd_tile_count[gid] = 0u;   // reset for graph replay
            __threadfence();
            const unsigned int c = atomicAdd(&g_cd_final_count, 1u);
            sFlag = (c == (unsigned int)(ngroups - 1));
        }
        __syncthreads();
        if (!sFlag) return;

        // ---- Final: parallel fixed-order sum of ngroups group sums ----
        __threadfence();
        float s2 = 0.0f;
        for (int i = tid; i < ngroups; i += CD_THREADS)
            s2 += g_cd_group[i];
#pragma unroll
        for (int off = 16; off > 0; off >>= 1)
            s2 += __shfl_down_sync(0xffffffffu, s2, off);
        if (lane == 0) red[wid] = s2;
        __syncthreads();
        if (tid == 0) {
            float v = 0.0f;
#pragma unroll
            for (int i = 0; i < CD_THREADS / 32; ++i) v += red[i];
            out[0] = v * scale;
            g_cd_final_count = 0u;       // reset for graph replay
        }
    }
}

extern "C" void kernel_launch(void* const* d_in, const int* in_sizes, int n_in,
                              void* d_out, int out_size) {
    const float* adv = (const float*)d_in[0];   // [B, K, 3] float32
    const float* ori = (const float*)d_in[1];   // [B, K, 3] float32
    const float* w   = (const float*)d_in[2];   // [B]       float32
    float* out = (float*)d_out;                 // scalar float32

    const int B = in_sizes[2];
    const int K = in_sizes[0] / (3 * B);

    const int ktiles = (K + CD_KCHUNK - 1) / CD_KCHUNK;
    const int blocks = B * CD_JS * ktiles;      // 8*16*8 = 1024 @ B=8,K=4096

    const float scale = 1.0f / ((float)B * (float)K);
    chamfer_main_kernel<<<blocks, CD_THREADS>>>(adv, ori, w, out,
                                                B, K, ktiles, scale);
}

// round 12
// speedup vs baseline: 1.2219x; 1.0607x over previous
#include <cuda_runtime.h>
#include <float.h>

// ChamferDist (adv->ori): loss = mean_b( w_b * mean_k( min_j ||adv[bk]-ori[bj]||^2 ) )
//
// min_j dist = a2_k + min_j (b2_j - 2 a_k.b_j).
// R10 = R9 main loop (128 thr, 4 consecutive pts/thread, JS=16, grid 1024,
// unroll-8 f32x2 hot loop) with the scratch/combine tail replaced by
// ORDER-INVARIANT atomic min:
//   key[point] : uint, monotonic encoding with smaller float = LARGER key,
//   key 0 == "+inf" (zero-init of __device__ globals -> first call correct).
//   Main CTAs: RED.MAX per point (min is order-independent -> deterministic).
//   Group (b,ktile) last-CTA: decode+sum 512 keys (2KB), reset keys to 0,
//   weight by w[b]. Final last group sums 64 group values -> scalar.
// Single launch, deterministic, graph-replay safe.

#define CD_THREADS 128
#define CD_PTS     4
#define CD_JS      16
#define CD_KCHUNK  512           // CD_THREADS * CD_PTS
#define CD_JCHUNK  256
#define CD_PAIRS   128           // CD_JCHUNK / 2
#define CD_MAX_PTS (1 << 17)     // B*K keys (uint)
#define CD_MAX_GROUPS  1024

__device__ unsigned int g_cd_key[CD_MAX_PTS];          // zero-init == +inf
__device__ float        g_cd_group[CD_MAX_GROUPS];
__device__ unsigned int g_cd_tile_count[CD_MAX_GROUPS];
__device__ unsigned int g_cd_final_count;

__device__ __forceinline__ unsigned long long pack_dup(float v) {
    unsigned long long r;
    asm("mov.b64 %0, {%1, %1};" : "=l"(r) : "f"(v));
    return r;
}
__device__ __forceinline__ unsigned long long fma2(unsigned long long a,
                                                   unsigned long long b,
                                                   unsigned long long c) {
    unsigned long long d;
    asm("fma.rn.f32x2 %0, %1, %2, %3;" : "=l"(d) : "l"(a), "l"(b), "l"(c));
    return d;
}

// Monotonic float->uint with smaller float => larger key; key 0 acts as +inf.
__device__ __forceinline__ unsigned int cd_enc(float f) {
    unsigned int u = __float_as_uint(f);
    unsigned int k = ((int)u < 0) ? ~u : (u ^ 0x80000000u);
    return ~k;
}
__device__ __forceinline__ float cd_dec(unsigned int key) {
    unsigned int k = ~key;
    return ((int)k < 0) ? __uint_as_float(k ^ 0x80000000u)
                        : __uint_as_float(~k);
}

__global__ __launch_bounds__(CD_THREADS)
void chamfer_main_kernel(const float* __restrict__ adv,
                         const float* __restrict__ ori,
                         const float* __restrict__ w,
                         float* __restrict__ out,
                         int B, int K, int ktiles, float scale) {
    __shared__ float4 sXY[CD_PAIRS];
    __shared__ float4 sZW[CD_PAIRS];
    __shared__ float  red[CD_THREADS / 32];
    __shared__ bool   sFlag;

    const int tid = threadIdx.x;
    const int kt  = blockIdx.x % ktiles;
    const int rem = blockIdx.x / ktiles;
    const int js  = rem % CD_JS;
    const int b   = rem / CD_JS;
    const int ngroups = B * ktiles;
    const int gid = b * ktiles + kt;

    const bool exactK = (K % CD_KCHUNK) == 0;

    // ---- Fill smem with this CTA's ori j-chunk (pair layout) ----
    const int j0g = js * CD_JCHUNK;
    int cl = K - j0g;
    if (cl > CD_JCHUNK) cl = CD_JCHUNK;
    if (cl < 0) cl = 0;
    const int pairsPad = (cl + 1) >> 1;

    const float* __restrict__ orib = ori + (size_t)b * K * 3;
    for (int p = tid; p < pairsPad; p += CD_THREADS) {
        const int j0 = 2 * p;
        const int j1 = (2 * p + 1 < cl) ? (2 * p + 1) : (cl - 1);
        const float x0 = orib[(j0g + j0) * 3 + 0];
        const float y0 = orib[(j0g + j0) * 3 + 1];
        const float z0 = orib[(j0g + j0) * 3 + 2];
        const float x1 = orib[(j0g + j1) * 3 + 0];
        const float y1 = orib[(j0g + j1) * 3 + 1];
        const float z1 = orib[(j0g + j1) * 3 + 2];
        sXY[p] = make_float4(-2.0f * x0, -2.0f * x1, -2.0f * y0, -2.0f * y1);
        sZW[p] = make_float4(-2.0f * z0, -2.0f * z1,
                             x0 * x0 + y0 * y0 + z0 * z0,
                             x1 * x1 + y1 * y1 + z1 * z1);
    }
    __syncthreads();

    // ---- 4 CONSECUTIVE adv points per thread (vector loads) ----
    const int kbase = kt * CD_KCHUNK + 4 * tid;
    float ax[CD_PTS], ay[CD_PTS], az[CD_PTS];
    const float* __restrict__ abase = adv + ((size_t)b * K + kbase) * 3;

    if (exactK && ((((size_t)abase) & 15) == 0)) {
        const float4* __restrict__ a4 = (const float4*)abase;
        const float4 q0 = a4[0];   // x0 y0 z0 x1
        const float4 q1 = a4[1];   // y1 z1 x2 y2
        const float4 q2 = a4[2];   // z2 x3 y3 z3
        ax[0] = q0.x; ay[0] = q0.y; az[0] = q0.z;
        ax[1] = q0.w; ay[1] = q1.x; az[1] = q1.y;
        ax[2] = q1.z; ay[2] = q1.w; az[2] = q2.x;
        ax[3] = q2.y; ay[3] = q2.z; az[3] = q2.w;
    } else {
#pragma unroll
        for (int u = 0; u < CD_PTS; ++u) {
            const int k = kbase + u;
            float x = 0.f, y = 0.f, z = 0.f;
            if (k < K) {
                x = abase[3 * u + 0]; y = abase[3 * u + 1]; z = abase[3 * u + 2];
            }
            ax[u] = x; ay[u] = y; az[u] = z;
        }
    }

    float a2[CD_PTS];
    unsigned long long axx[CD_PTS], ayy[CD_PTS], azz[CD_PTS];
#pragma unroll
    for (int u = 0; u < CD_PTS; ++u) {
        a2[u]  = ax[u] * ax[u] + ay[u] * ay[u] + az[u] * az[u];
        axx[u] = pack_dup(ax[u]); ayy[u] = pack_dup(ay[u]); azz[u] = pack_dup(az[u]);
    }

    float mlo[CD_PTS], mhi[CD_PTS];
#pragma unroll
    for (int u = 0; u < CD_PTS; ++u) { mlo[u] = FLT_MAX; mhi[u] = FLT_MAX; }

    const ulonglong2* __restrict__ pXY = (const ulonglong2*)sXY;
    const ulonglong2* __restrict__ pZW = (const ulonglong2*)sZW;

    if (pairsPad == CD_PAIRS) {
#pragma unroll 8
        for (int p = 0; p < CD_PAIRS; ++p) {
            const ulonglong2 A = pXY[p];   // (x0,x1) , (y0,y1)
            const ulonglong2 Z = pZW[p];   // (z0,z1) , (b2_0,b2_1)
#pragma unroll
            for (int u = 0; u < CD_PTS; ++u) {
                union { unsigned long long u64; float2 f2; } t;
                t.u64 = fma2(azz[u], Z.x, Z.y);
                t.u64 = fma2(ayy[u], A.y, t.u64);
                t.u64 = fma2(axx[u], A.x, t.u64);
                mlo[u] = fminf(mlo[u], t.f2.x);
                mhi[u] = fminf(mhi[u], t.f2.y);
            }
        }
    } else {
#pragma unroll 4
        for (int p = 0; p < pairsPad; ++p) {
            const ulonglong2 A = pXY[p];
            const ulonglong2 Z = pZW[p];
#pragma unroll
            for (int u = 0; u < CD_PTS; ++u) {
                union { unsigned long long u64; float2 f2; } t;
                t.u64 = fma2(azz[u], Z.x, Z.y);
                t.u64 = fma2(ayy[u], A.y, t.u64);
                t.u64 = fma2(axx[u], A.x, t.u64);
                mlo[u] = fminf(mlo[u], t.f2.x);
                mhi[u] = fminf(mhi[u], t.f2.y);
            }
        }
    }

    // ---- Order-invariant min merge via atomicMax on monotone keys ----
    if (exactK) {
#pragma unroll
        for (int u = 0; u < CD_PTS; ++u) {
            const float m = fminf(mlo[u], mhi[u]) + a2[u];
            atomicMax(&g_cd_key[(size_t)b * K + kbase + u], cd_enc(m));
        }
    } else {
#pragma unroll
        for (int u = 0; u < CD_PTS; ++u) {
            const int k = kbase + u;
            if (k < K) {
                const float m = fminf(mlo[u], mhi[u]) + a2[u];
                atomicMax(&g_cd_key[(size_t)b * K + k], cd_enc(m));
            }
        }
    }

    // ---- Per-(b,ktile) group combine by the group's last CTA ----
    __threadfence();
    if (tid == 0) {
        const unsigned int c = atomicAdd(&g_cd_tile_count[gid], 1u);
        sFlag = (c == (unsigned int)(CD_JS - 1));
    }
    __syncthreads();
    if (!sFlag) return;
    __threadfence();

    {
        const int kb = kt * CD_KCHUNK;
        int npts = K - kb;
        if (npts > CD_KCHUNK) npts = CD_KCHUNK;
        unsigned int* __restrict__ base = g_cd_key + (size_t)b * K + kb;

        float s = 0.0f;
        if (npts == CD_KCHUNK) {
            // 512 keys: one uint4 per thread.
            uint4* __restrict__ b4 = (uint4*)base;
            const uint4 v = b4[tid];
            s = cd_dec(v.x) + cd_dec(v.y) + cd_dec(v.z) + cd_dec(v.w);
            b4[tid] = make_uint4(0u, 0u, 0u, 0u);   // reset = +inf for replay
        } else {
            for (int i = tid; i < npts; i += CD_THREADS) {
                s += cd_dec(base[i]);
                base[i] = 0u;
            }
        }

        const int lane = tid & 31, wid = tid >> 5;
#pragma unroll
        for (int off = 16; off > 0; off >>= 1)
            s += __shfl_down_sync(0xffffffffu, s, off);
        if (lane == 0) red[wid] = s;
        __syncthreads();
        if (tid == 0) {
            float v = 0.0f;
#pragma unroll
            for (int i = 0; i < CD_THREADS / 32; ++i) v += red[i];
            g_cd_group[gid] = v * w[b];
            g_cd_tile_count[gid] = 0u;   // reset for graph replay
            __threadfence();
            const unsigned int c = atomicAdd(&g_cd_final_count, 1u);
            sFlag = (c == (unsigned int)(ngroups - 1));
        }
        __syncthreads();
        if (!sFlag) return;

        // ---- Final: parallel fixed-order sum of ngroups group sums ----
        __threadfence();
        float s2 = 0.0f;
        for (int i = tid; i < ngroups; i += CD_THREADS)
            s2 += g_cd_group[i];
#pragma unroll
        for (int off = 16; off > 0; off >>= 1)
            s2 += __shfl_down_sync(0xffffffffu, s2, off);
        if (lane == 0) red[wid] = s2;
        __syncthreads();
        if (tid == 0) {
            float v = 0.0f;
#pragma unroll
            for (int i = 0; i < CD_THREADS / 32; ++i) v += red[i];
            out[0] = v * scale;
            g_cd_final_count = 0u;       // reset for graph replay
        }
    }
}

extern "C" void kernel_launch(void* const* d_in, const int* in_sizes, int n_in,
                              void* d_out, int out_size) {
    const float* adv = (const float*)d_in[0];   // [B, K, 3] float32
    const float* ori = (const float*)d_in[1];   // [B, K, 3] float32
    const float* w   = (const float*)d_in[2];   // [B]       float32
    float* out = (float*)d_out;                 // scalar float32

    const int B = in_sizes[2];
    const int K = in_sizes[0] / (3 * B);

    const int ktiles = (K + CD_KCHUNK - 1) / CD_KCHUNK;
    const int blocks = B * CD_JS * ktiles;      // 8*16*8 = 1024 @ B=8,K=4096

    const float scale = 1.0f / ((float)B * (float)K);
    chamfer_main_kernel<<<blocks, CD_THREADS>>>(adv, ori, w, out,
                                                B, K, ktiles, scale);
}